// round 9
// baseline (speedup 1.0000x reference)
#include <cuda_runtime.h>
#include <cuda_bf16.h>

// ShiftLayer: out[b,t,c] = in[b, t+off[c], c], off[c] = {0,-1,+1} for c%3 = {0,1,2},
// zero padding at sequence ends. B=8, L=8192, C=384, fp32.
//
// Steady-state L2 residency policy (harness replays the graph on the same
// input; the 100.7MB input fits the 126MB L2):
//   - loads:  createpolicy.fractional.L2::evict_last(1.0) + ld.L2::cache_hint
//             -> pin input lines in L2 across graph replays
//   - stores: createpolicy.fractional.L2::evict_first(1.0) + st.L2::cache_hint
//             -> write-once output streams through without churning the input
// (The bare ld.global.L2::evict_last modifier requires 256-bit accesses on
// sm_103a; the cache_hint form works with .v4.f32.)
//
// Warp per (batch, 16-row chunk, 128-channel group); lane owns the float4 at
// channel 4*lane+128*g. Rows stream through registers (prev/cur/next rotation),
// fully coalesced 512B LDG.128/STG.128, no smem, no barriers.

#define B_DIM 8
#define L_DIM 8192
#define C_DIM 384
#define T_R   16                        // rows per warp chunk
#define GROUPS 3                        // 128-channel column groups
#define WARPS_PER_BLOCK 4
#define THREADS (WARPS_PER_BLOCK * 32)

__device__ __forceinline__ unsigned long long mk_policy_last() {
    unsigned long long pol;
    asm("createpolicy.fractional.L2::evict_last.b64 %0, 1.0;" : "=l"(pol));
    return pol;
}
__device__ __forceinline__ unsigned long long mk_policy_first() {
    unsigned long long pol;
    asm("createpolicy.fractional.L2::evict_first.b64 %0, 1.0;" : "=l"(pol));
    return pol;
}

__device__ __forceinline__ float4 ldg4(const float* p, unsigned long long pol) {
    float4 v;
    asm volatile("ld.global.L2::cache_hint.v4.f32 {%0,%1,%2,%3}, [%4], %5;"
                 : "=f"(v.x), "=f"(v.y), "=f"(v.z), "=f"(v.w)
                 : "l"(p), "l"(pol));
    return v;
}
__device__ __forceinline__ void stg4(float* p, float4 v, unsigned long long pol) {
    asm volatile("st.global.L2::cache_hint.v4.f32 [%0], {%1,%2,%3,%4}, %5;"
                 :: "l"(p), "f"(v.x), "f"(v.y), "f"(v.z), "f"(v.w), "l"(pol)
                 : "memory");
}

// Component j of this lane's float4 has channel residue (m + j) % 3.
// residue 0 -> cur, 1 -> prev (out[t]=in[t-1]), 2 -> next (out[t]=in[t+1]).
__device__ __forceinline__ float4 route(float4 p, float4 c, float4 n,
                                        bool is1, bool is2) {
    float4 o;
    o.x = is1 ? p.x : (is2 ? n.x : c.x);   // residue m
    o.y = is1 ? n.y : (is2 ? c.y : p.y);   // residue m+1
    o.z = is1 ? c.z : (is2 ? p.z : n.z);   // residue m+2
    o.w = is1 ? p.w : (is2 ? n.w : c.w);   // residue m
    return o;
}

__global__ __launch_bounds__(THREADS)
void ShiftLayer_66932770341347_kernel(const float* __restrict__ in,
                                      float* __restrict__ out) {
    const int warp = blockIdx.x * WARPS_PER_BLOCK + (threadIdx.x >> 5);
    const int lane = threadIdx.x & 31;

    const int g     = warp % GROUPS;                     // column group 0..2
    const int chunk = warp / GROUPS;
    const int chunks_per_b = L_DIM / T_R;                // 512
    const int b  = chunk / chunks_per_b;
    const int t0 = (chunk % chunks_per_b) * T_R;

    const size_t row0 = ((size_t)b * L_DIM + t0) * C_DIM + 4 * lane + 128 * g;
    const float* base  = in  + row0;
    float*       obase = out + row0;

    const unsigned long long pol_ld = mk_policy_last();
    const unsigned long long pol_st = mk_policy_first();

    // Base channel residue: (4*lane + 128*g) % 3 == (lane + 2*g) % 3
    const int m = (lane + 2 * g) % 3;
    const bool is1 = (m == 1), is2 = (m == 2);

    const float4 z = make_float4(0.f, 0.f, 0.f, 0.f);

    float4 P, C, N;

    // Prologue: prev = row t0-1 (zeros at sequence start), cur = row t0.
    P = (t0 > 0) ? ldg4(base - C_DIM, pol_ld) : z;
    C = ldg4(base, pol_ld);

    // Rows t0 .. t0+T_R-2: next row always in-range.
    #pragma unroll
    for (int r = 0; r < T_R - 1; ++r) {
        N = ldg4(base + (size_t)(r + 1) * C_DIM, pol_ld);
        stg4(obase + (size_t)r * C_DIM, route(P, C, N, is1, is2), pol_st);
        P = C;
        C = N;
    }

    // Last row of the chunk: next row may be past the sequence end.
    N = (t0 + T_R < L_DIM) ? ldg4(base + (size_t)T_R * C_DIM, pol_ld) : z;
    stg4(obase + (size_t)(T_R - 1) * C_DIM, route(P, C, N, is1, is2), pol_st);
}

extern "C" void kernel_launch(void* const* d_in, const int* in_sizes, int n_in,
                              void* d_out, int out_size) {
    const float* mem = (const float*)d_in[0];
    float* out = (float*)d_out;
    (void)in_sizes; (void)n_in; (void)out_size;

    const int total_warps = B_DIM * (L_DIM / T_R) * GROUPS;   // 12288
    const int grid = total_warps / WARPS_PER_BLOCK;           // 3072 blocks
    ShiftLayer_66932770341347_kernel<<<grid, THREADS>>>(mem, out);
}

// round 10
// speedup vs baseline: 1.0633x; 1.0633x over previous
#include <cuda_runtime.h>
#include <cuda_bf16.h>

// ShiftLayer: out[b,t,c] = in[b, t+off[c], c], off[c] = {0,-1,+1} for c%3 = {0,1,2},
// zero padding at sequence ends. B=8, L=8192, C=384, fp32.
//
// Flat stateless kernel: one thread per output float4. Each thread issues 3
// INDEPENDENT LDG.128 (same channel slot in rows t-1, t, t+1 = flat +/-384
// floats), routes components by the static per-channel residue, and does one
// evict-first store. No loops, no carried registers: ~16 live regs, so the
// 3 loads stay in flight together (per-warp MLP=3 -- the thing the 32-reg
// clamp forbade in the rotation versions). Row reuse between neighboring
// threads is absorbed by L1/L2 (L1 was at 40%, lots of headroom); DRAM
// traffic stays ~1x read + 1x write. Stores use .cs (evict-first), the one
// cache policy that measurably helped steady-state harness time (R7).

#define B_DIM 8
#define L_DIM 8192
#define C_DIM 384
#define CV    (C_DIM / 4)               // 96 float4 per row
#define THREADS 256

__device__ __forceinline__ float4 ldg4(const float* p) {
    return *reinterpret_cast<const float4*>(p);
}
__device__ __forceinline__ void stg4(float* p, float4 v) {
    __stcs(reinterpret_cast<float4*>(p), v);   // evict-first: protect L2 input residency
}

// Component j of this float4 has channel residue (m + j) % 3.
// residue 0 -> cur, 1 -> prev (out[t]=in[t-1]), 2 -> next (out[t]=in[t+1]).
__device__ __forceinline__ float4 route(float4 p, float4 c, float4 n,
                                        bool is1, bool is2) {
    float4 o;
    o.x = is1 ? p.x : (is2 ? n.x : c.x);   // residue m
    o.y = is1 ? n.y : (is2 ? c.y : p.y);   // residue m+1
    o.z = is1 ? c.z : (is2 ? p.z : n.z);   // residue m+2
    o.w = is1 ? p.w : (is2 ? n.w : c.w);   // residue m
    return o;
}

__global__ __launch_bounds__(THREADS)
void ShiftLayer_66932770341347_kernel(const float* __restrict__ in,
                                      float* __restrict__ out) {
    const int id = blockIdx.x * THREADS + threadIdx.x;   // float4 index, < B*L*CV

    // Decompose: id = ((b*L + t) * CV) + cc4
    const int cc4 = id % CV;                 // float4 slot within the row
    const int t   = (id / CV) % L_DIM;       // sequence position

    // Base channel residue: (4*cc4) % 3
    const int m = (4 * cc4) % 3;
    const bool is1 = (m == 1), is2 = (m == 2);

    const float* p = in + (size_t)id * 4;    // this thread's cur float4
    const float4 z = make_float4(0.f, 0.f, 0.f, 0.f);

    // Three independent loads (rows t-1, t, t+1 at the same channel slot).
    float4 P = (t > 0)         ? ldg4(p - C_DIM) : z;
    float4 C = ldg4(p);
    float4 N = (t < L_DIM - 1) ? ldg4(p + C_DIM) : z;

    stg4(out + (size_t)id * 4, route(P, C, N, is1, is2));
}

extern "C" void kernel_launch(void* const* d_in, const int* in_sizes, int n_in,
                              void* d_out, int out_size) {
    const float* mem = (const float*)d_in[0];
    float* out = (float*)d_out;
    (void)in_sizes; (void)n_in; (void)out_size;

    const int total = B_DIM * L_DIM * CV;            // 786432 float4s
    const int grid  = total / THREADS;               // 3072 blocks
    ShiftLayer_66932770341347_kernel<<<grid, THREADS>>>(mem, out);
}

// round 11
// speedup vs baseline: 1.1045x; 1.0387x over previous
#include <cuda_runtime.h>
#include <cuda_bf16.h>
#include <cstdint>

// ShiftLayer: out[b,t,c] = in[b, t+off[c], c], off[c] = {0,-1,+1} for c%3 = {0,1,2},
// zero padding at sequence ends. B=8, L=8192, C=384, fp32.
//
// 256-bit version: one thread per 8 consecutive channels (float8). Each thread
// issues 3 independent LDG.256 (rows t-1, t, t+1 at its 32B channel slot),
// routes components by the static per-channel residue (pure selects on u32),
// and does one STG.256 with L2::evict_first (the policy+width combo sm_103a
// ptxas natively supports, and the one cache policy that measurably helped
// steady-state harness time). Halves LSU instructions / L1 wavefronts per byte
// vs the float4 version and doubles bytes-in-flight per load slot.
// __launch_bounds__(256,4) caps regs at 64 so ptxas can't re-serialize the
// loads via its 32-reg clamp (R4 failure mode).

#define B_DIM 8
#define L_DIM 8192
#define C_DIM 384
#define SLOTS (C_DIM / 8)               // 48 float8 slots per row
#define THREADS 256

__device__ __forceinline__ void ld8(uint32_t* d, const float* p) {
    asm volatile("ld.global.v8.b32 {%0,%1,%2,%3,%4,%5,%6,%7}, [%8];"
                 : "=r"(d[0]), "=r"(d[1]), "=r"(d[2]), "=r"(d[3]),
                   "=r"(d[4]), "=r"(d[5]), "=r"(d[6]), "=r"(d[7])
                 : "l"(p));
}
__device__ __forceinline__ void st8(float* p, const uint32_t* v) {
    asm volatile("st.global.L2::evict_first.v8.b32 [%0], {%1,%2,%3,%4,%5,%6,%7,%8};"
                 :: "l"(p),
                    "r"(v[0]), "r"(v[1]), "r"(v[2]), "r"(v[3]),
                    "r"(v[4]), "r"(v[5]), "r"(v[6]), "r"(v[7])
                 : "memory");
}

__global__ __launch_bounds__(THREADS, 4)
void ShiftLayer_66932770341347_kernel(const float* __restrict__ in,
                                      float* __restrict__ out) {
    const int id = blockIdx.x * THREADS + threadIdx.x;   // float8 index

    const int row = id / SLOTS;                 // b*L + t
    const int s   = id - row * SLOTS;           // slot 0..47
    const int t   = row & (L_DIM - 1);          // L is a power of two

    // Base channel residue: (8*s) % 3 == (2*s) % 3
    const int m = (2 * s) % 3;
    const bool is1 = (m == 1), is2 = (m == 2);

    const float* p = in + (size_t)id * 8;

    uint32_t P[8], C[8], N[8];
    ld8(C, p);
    if (t > 0) {
        ld8(P, p - C_DIM);
    } else {
        #pragma unroll
        for (int j = 0; j < 8; ++j) P[j] = 0u;
    }
    if (t < L_DIM - 1) {
        ld8(N, p + C_DIM);
    } else {
        #pragma unroll
        for (int j = 0; j < 8; ++j) N[j] = 0u;
    }

    // Component j has residue (m + j) % 3; residue 0 -> C, 1 -> P, 2 -> N.
    // Selection depends only on j%3 and (is1, is2):
    uint32_t o[8];
    #pragma unroll
    for (int j = 0; j < 8; ++j) {
        const int jc = j % 3;
        if (jc == 0)      o[j] = is1 ? P[j] : (is2 ? N[j] : C[j]);
        else if (jc == 1) o[j] = is1 ? N[j] : (is2 ? C[j] : P[j]);
        else              o[j] = is1 ? C[j] : (is2 ? P[j] : N[j]);
    }

    st8(out + (size_t)id * 8, o);
}

extern "C" void kernel_launch(void* const* d_in, const int* in_sizes, int n_in,
                              void* d_out, int out_size) {
    const float* mem = (const float*)d_in[0];
    float* out = (float*)d_out;
    (void)in_sizes; (void)n_in; (void)out_size;

    const int total = B_DIM * L_DIM * SLOTS;          // 3,145,728 float8s
    const int grid  = total / THREADS;                // 12288 blocks
    ShiftLayer_66932770341347_kernel<<<grid, THREADS>>>(mem, out);
}

// round 12
// speedup vs baseline: 1.1145x; 1.0091x over previous
#include <cuda_runtime.h>
#include <cuda_bf16.h>
#include <cstdint>

// ShiftLayer: out[b,t,c] = in[b, t+off[c], c], off[c] = {0,-1,+1} for c%3 = {0,1,2},
// zero padding at sequence ends. B=8, L=8192, C=384, fp32.
//
// Paired-row 256-bit kernel: one thread produces TWO consecutive output rows
// (t, t+1) at one 8-channel slot. It issues 4 independent LDG.256 (rows
// t-1, t, t+1, t+2), routes by the static per-channel residue, and does two
// STG.256 with L2::evict_first. Versus the 1-row flat version this cuts read
// amplification 3x -> 2x (less L1/L2 traffic, the steady-state limiter) and
// halves index math per byte, while keeping all load slots independent (no
// loop-carried rotation for ptxas to serialize). ~48 live regs under a
// __launch_bounds__(256,4) 64-reg envelope.

#define B_DIM 8
#define L_DIM 8192
#define C_DIM 384
#define SLOTS (C_DIM / 8)               // 48 float8 slots per row
#define THREADS 256

__device__ __forceinline__ void ld8(uint32_t* d, const float* p) {
    asm volatile("ld.global.v8.b32 {%0,%1,%2,%3,%4,%5,%6,%7}, [%8];"
                 : "=r"(d[0]), "=r"(d[1]), "=r"(d[2]), "=r"(d[3]),
                   "=r"(d[4]), "=r"(d[5]), "=r"(d[6]), "=r"(d[7])
                 : "l"(p));
}
__device__ __forceinline__ void st8(float* p, const uint32_t* v) {
    asm volatile("st.global.L2::evict_first.v8.b32 [%0], {%1,%2,%3,%4,%5,%6,%7,%8};"
                 :: "l"(p),
                    "r"(v[0]), "r"(v[1]), "r"(v[2]), "r"(v[3]),
                    "r"(v[4]), "r"(v[5]), "r"(v[6]), "r"(v[7])
                 : "memory");
}

// Component j has channel residue (m + j) % 3; residue 0 -> C, 1 -> P, 2 -> N.
__device__ __forceinline__ void route8(uint32_t* o, const uint32_t* P,
                                       const uint32_t* C, const uint32_t* N,
                                       bool is1, bool is2) {
    #pragma unroll
    for (int j = 0; j < 8; ++j) {
        const int jc = j % 3;
        if (jc == 0)      o[j] = is1 ? P[j] : (is2 ? N[j] : C[j]);
        else if (jc == 1) o[j] = is1 ? N[j] : (is2 ? C[j] : P[j]);
        else              o[j] = is1 ? C[j] : (is2 ? P[j] : N[j]);
    }
}

__global__ __launch_bounds__(THREADS, 4)
void ShiftLayer_66932770341347_kernel(const float* __restrict__ in,
                                      float* __restrict__ out) {
    const int id = blockIdx.x * THREADS + threadIdx.x;   // (row-pair, slot) index

    const int pair = id / SLOTS;                 // b*(L/2) + t/2
    const int s    = id - pair * SLOTS;          // slot 0..47
    const int t    = (pair & (L_DIM / 2 - 1)) * 2;   // even row in [0, L)

    // Base channel residue: (8*s) % 3 == (2*s) % 3 (same for both rows)
    const int m = (2 * s) % 3;
    const bool is1 = (m == 1), is2 = (m == 2);

    // Flat element offset of (row t, slot s) for this pair's batch.
    const size_t base = ((size_t)(pair / (L_DIM / 2)) * L_DIM + t) * C_DIM + 8 * s;
    const float* p = in + base;

    uint32_t A[8], Bv[8], Cv[8], D[8];           // rows t-1, t, t+1, t+2
    ld8(Bv, p);
    ld8(Cv, p + C_DIM);
    if (t > 0) {
        ld8(A, p - C_DIM);
    } else {
        #pragma unroll
        for (int j = 0; j < 8; ++j) A[j] = 0u;
    }
    if (t + 2 < L_DIM) {
        ld8(D, p + 2 * C_DIM);
    } else {
        #pragma unroll
        for (int j = 0; j < 8; ++j) D[j] = 0u;
    }

    uint32_t o0[8], o1[8];
    route8(o0, A,  Bv, Cv, is1, is2);            // output row t
    route8(o1, Bv, Cv, D,  is1, is2);            // output row t+1

    float* q = out + base;
    st8(q,         o0);
    st8(q + C_DIM, o1);
}

extern "C" void kernel_launch(void* const* d_in, const int* in_sizes, int n_in,
                              void* d_out, int out_size) {
    const float* mem = (const float*)d_in[0];
    float* out = (float*)d_out;
    (void)in_sizes; (void)n_in; (void)out_size;

    const int total = B_DIM * (L_DIM / 2) * SLOTS;    // 1,572,864 threads
    const int grid  = total / THREADS;                // 6144 blocks
    ShiftLayer_66932770341347_kernel<<<grid, THREADS>>>(mem, out);
}